// round 9
// baseline (speedup 1.0000x reference)
#include <cuda_runtime.h>
#include <cstdint>

#define Bn 256
#define Tn 128
#define Dn 300
#define Hn 512
#define G4 2048
#define OUTD 200

typedef unsigned long long u64;

// -------- static scratch --------
__device__ float g_X[2][Tn * Bn * G4];        // input projections [t][b][2048]
__device__ float g_H1[2][Tn * Bn * Hn];       // layer1 h row-major (final gather)
// pair-layout h images, tf32-pre-rounded:
// [layer][enc][t][mhalf][row*256 + k8grp*4 + tig] float2 = {h[k], h[k+4]}
__device__ float2 g_Hp[2][2][Tn][2][128 * 256];
// W fragment images in mma B-reg order: [layer][e][s][idx<16384] float2
__device__ float2 g_Wf[2][2][32][16384];
// cell state [e][b][unit]
__device__ float g_c[2][Bn][Hn];

// -------- tf32 / mma helpers --------
__device__ __forceinline__ uint32_t cvt_tf32(float f) {
    uint32_t r;
    asm("cvt.rna.tf32.f32 %0, %1;" : "=r"(r) : "f"(f));
    return r;
}
__device__ __forceinline__ float tf32f(float f) {
    return __uint_as_float(cvt_tf32(f));
}
__device__ __forceinline__ void mma8(float* d, uint32_t a0, uint32_t a1,
                                     uint32_t a2, uint32_t a3,
                                     uint32_t b0, uint32_t b1) {
    asm volatile(
        "mma.sync.aligned.m16n8k8.row.col.f32.tf32.tf32.f32 "
        "{%0,%1,%2,%3}, {%4,%5,%6,%7}, {%8,%9}, {%0,%1,%2,%3};"
        : "+f"(d[0]), "+f"(d[1]), "+f"(d[2]), "+f"(d[3])
        : "r"(a0), "r"(a1), "r"(a2), "r"(a3), "r"(b0), "r"(b1));
}
__device__ __forceinline__ uint32_t smem_u32(const void* p) {
    uint32_t a;
    asm("{ .reg .u64 t; cvta.to.shared.u64 t, %1; cvt.u32.u64 %0, t; }"
        : "=r"(a) : "l"(p));
    return a;
}
__device__ __forceinline__ u64 gaddr(const void* p) {
    u64 g;
    asm("cvta.to.global.u64 %0, %1;" : "=l"(g) : "l"(p));
    return g;
}

// -------- fast activations --------
__device__ __forceinline__ float fast_ex2(float x) {
    float y; asm("ex2.approx.f32 %0, %1;" : "=f"(y) : "f"(x)); return y;
}
__device__ __forceinline__ float fast_rcp(float x) {
    float y; asm("rcp.approx.f32 %0, %1;" : "=f"(y) : "f"(x)); return y;
}
__device__ __forceinline__ float sigf(float x) {
    return fast_rcp(1.0f + fast_ex2(-1.4426950408889634f * x));
}
__device__ __forceinline__ float tanhfast(float x) {
    return 2.0f * fast_rcp(1.0f + fast_ex2(-2.8853900817779268f * x)) - 1.0f;
}

__device__ __forceinline__ float4 gload4(const float* p, int k0, int K) {
    if (k0 + 3 < K) return *(const float4*)p;
    float4 v = make_float4(0.f, 0.f, 0.f, 0.f);
    if (k0 < K)     v.x = p[0];
    if (k0 + 1 < K) v.y = p[1];
    if (k0 + 2 < K) v.z = p[2];
    return v;
}

// ============================================================================
// W fragment prep (once per layer): g_Wf[layer][e][s] in mma B-reg order.
// ============================================================================
__global__ __launch_bounds__(256) void wprep(
    const float* __restrict__ WhL, const float* __restrict__ WhR, int layer)
{
    const int e = blockIdx.y, s = blockIdx.x;
    const float* Wh = e ? WhR : WhL;
    const int u0 = s * 16;
    float2* dst = &g_Wf[layer][e][s][0];
#pragma unroll 4
    for (int i = 0; i < 64; i++) {
        int idx = threadIdx.x + 256 * i;
        int ln = idx & 31, nt = (idx >> 5) & 7, ks = idx >> 8;
        int n = nt * 8 + (ln >> 2);
        int k = ks * 8 + (ln & 3);
        int col = ((n >> 4) << 9) + u0 + (n & 15);
        uint32_t b0 = cvt_tf32(Wh[(size_t)k * G4 + col]);
        uint32_t b1 = cvt_tf32(Wh[(size_t)(k + 4) * G4 + col]);
        dst[idx] = make_float2(__uint_as_float(b0), __uint_as_float(b1));
    }
}

// ============================================================================
// Input-projection GEMM via tf32 mma.sync (unchanged, proven).
// ============================================================================
#define XP_PITCH 10

__global__ __launch_bounds__(256) void xproj_mma(
    const float* __restrict__ AL, const float* __restrict__ AR,
    const float* __restrict__ WL, const float* __restrict__ WR,
    const float* __restrict__ bL, const float* __restrict__ bR,
    int K, int mode)
{
    __shared__ __align__(16) float2 Apair[128 * XP_PITCH];
    __shared__ __align__(16) float2 Wpair[128 * XP_PITCH];

    const int e = blockIdx.z;
    const float* A    = e ? AR : AL;
    const float* W    = e ? WR : WL;
    const float* bias = e ? bR : bL;
    float* Out = g_X[e];

    const int m0 = blockIdx.x * 128;
    const int n0 = blockIdx.y * 128;
    const int tid = threadIdx.x, lane = tid & 31, wid = tid >> 5;
    const int wm = wid & 1, wn = wid >> 1;
    const int gid = lane >> 2, tig = lane & 3;

    const int tt = m0 >> 8, mh = (m0 >> 7) & 1;

    float d[4][4][4];
#pragma unroll
    for (int a = 0; a < 4; a++)
#pragma unroll
        for (int b = 0; b < 4; b++)
#pragma unroll
            for (int c = 0; c < 4; c++) d[a][b][c] = 0.0f;

    const int arow = tid >> 1, ag = tid & 1;
    const int wg = tid >> 7, wtk = (tid >> 5) & 3, wcc = tid & 31;

    const int nk = (K + 15) >> 4;
    for (int kc16 = 0; kc16 < nk; kc16++) {
        const int kc = kc16 * 16;
        __syncthreads();
        if (mode == 0) {
            int b = (m0 & 255) + arow;
            const float* ap = A + ((size_t)b * Tn + tt) * K + kc + ag * 8;
            int kb = kc + ag * 8;
            float4 lo = (kb     < K) ? gload4(ap, kb, K)
                                     : make_float4(0.f, 0.f, 0.f, 0.f);
            float4 hi = (kb + 4 < K) ? gload4(ap + 4, kb + 4, K)
                                     : make_float4(0.f, 0.f, 0.f, 0.f);
            float2* dst = &Apair[arow * XP_PITCH + ag * 4];
            dst[0] = make_float2(tf32f(lo.x), tf32f(hi.x));
            dst[1] = make_float2(tf32f(lo.y), tf32f(hi.y));
            dst[2] = make_float2(tf32f(lo.z), tf32f(hi.z));
            dst[3] = make_float2(tf32f(lo.w), tf32f(hi.w));
        } else {
            const float4* src = (const float4*)
                &g_Hp[0][e][tt][mh][(size_t)arow * 256 + ((kc >> 3) + ag) * 4];
            float4 v0 = src[0], v1 = src[1];
            float4* dst = (float4*)&Apair[arow * XP_PITCH + ag * 4];
            dst[0] = v0;
            dst[1] = v1;
        }
        {
            int k1 = kc + wg * 8 + wtk, k2 = k1 + 4;
            const float* wp1 = W + (size_t)k1 * G4 + n0 + wcc * 4;
            const float* wp2 = W + (size_t)k2 * G4 + n0 + wcc * 4;
            float4 lo = (k1 < K) ? *(const float4*)wp1
                                 : make_float4(0.f, 0.f, 0.f, 0.f);
            float4 hi = (k2 < K) ? *(const float4*)wp2
                                 : make_float4(0.f, 0.f, 0.f, 0.f);
            int c0 = wcc * 4, pidx = wg * 4 + wtk;
            Wpair[(c0 + 0) * XP_PITCH + pidx] = make_float2(tf32f(lo.x), tf32f(hi.x));
            Wpair[(c0 + 1) * XP_PITCH + pidx] = make_float2(tf32f(lo.y), tf32f(hi.y));
            Wpair[(c0 + 2) * XP_PITCH + pidx] = make_float2(tf32f(lo.z), tf32f(hi.z));
            Wpair[(c0 + 3) * XP_PITCH + pidx] = make_float2(tf32f(lo.w), tf32f(hi.w));
        }
        __syncthreads();
#pragma unroll
        for (int g = 0; g < 2; g++) {
            uint2 bf[4];
#pragma unroll
            for (int j = 0; j < 4; j++) {
                int col = wn * 32 + j * 8 + gid;
                bf[j] = *(const uint2*)&Wpair[col * XP_PITCH + g * 4 + tig];
            }
#pragma unroll
            for (int ms = 0; ms < 4; ms++) {
                int R = wm * 64 + ms * 16;
                uint2 alo = *(const uint2*)&Apair[(R + gid) * XP_PITCH + g * 4 + tig];
                uint2 ahi = *(const uint2*)&Apair[(R + 8 + gid) * XP_PITCH + g * 4 + tig];
#pragma unroll
                for (int j = 0; j < 4; j++)
                    mma8(d[ms][j], alo.x, ahi.x, alo.y, ahi.y, bf[j].x, bf[j].y);
            }
        }
    }

#pragma unroll
    for (int ms = 0; ms < 4; ms++) {
        int r = m0 + wm * 64 + ms * 16 + gid;
#pragma unroll
        for (int j = 0; j < 4; j++) {
            int n = n0 + wn * 32 + j * 8 + tig * 2;
            float2 bv = *(const float2*)&bias[n];
            *(float2*)&Out[(size_t)r * G4 + n] =
                make_float2(d[ms][j][0] + bv.x, d[ms][j][1] + bv.y);
            *(float2*)&Out[(size_t)(r + 8) * G4 + n] =
                make_float2(d[ms][j][2] + bv.x, d[ms][j][3] + bv.y);
        }
    }
}

// ============================================================================
// Per-step LSTM kernel (one launch per timestep; kernel boundary = barrier).
// 128 CTAs = e(2) x m(2) x s(32). CTA: M=128 x N=64 x K=512.
// W + h fragments cp.async-streamed from global images in 16 K=32 chunks,
// 3-stage ring. Cell state in g_c; X + c prefetched at kernel start.
// ============================================================================
#define A_ST_BYTES 20480                       // 128 rows x 10 f4 (8 data + 2 pad)
#define W_ST_BYTES 8192                        // 4 k8 x 8 nt x 32 lanes x f2
#define STG_BYTES  (A_ST_BYTES + W_ST_BYTES)   // 28672
#define SMEM_STEP  (3 * STG_BYTES)             // 86016
#define A2_PITCH   20                          // float2 pitch per A row

__global__ __launch_bounds__(256, 1) void lstm_step(int t, int layer)
{
    extern __shared__ __align__(16) char sm[];
    float* zs = (float*)sm;                    // aliases stages (post-GEMM)
    const uint32_t smb = smem_u32(sm);

    const int tid = threadIdx.x, lane = tid & 31, wid = tid >> 5;
    const int wm = wid >> 1, wn = wid & 1;     // 4 x 2 warp grid
    const int gid = lane >> 2, tig = lane & 3;
    const int e = blockIdx.x >> 6;
    const int m = (blockIdx.x >> 5) & 1;
    const int s = blockIdx.x & 31;
    const int m0 = m * 128, u0 = s * 16;
    const int eu = tid & 15, erg = tid >> 4;

    // ---- prefetch X gates + cell state (consumed after GEMM) ----
    float xg[4][8], creg[8];
    {
        const float* Xt = g_X[e] + ((size_t)t * Bn + m0) * G4 + u0;
#pragma unroll
        for (int q = 0; q < 8; q++) {
            const float* Xb = Xt + (size_t)(erg + 16 * q) * G4;
            xg[0][q] = Xb[eu];
            xg[1][q] = Xb[512 + eu];
            xg[2][q] = Xb[1024 + eu];
            xg[3][q] = Xb[1536 + eu];
        }
    }
    if (t > 0) {
#pragma unroll
        for (int q = 0; q < 8; q++)
            creg[q] = g_c[e][m0 + erg + 16 * q][u0 + eu];
    } else {
#pragma unroll
        for (int q = 0; q < 8; q++) creg[q] = 0.0f;
    }

    if (t > 0) {
        float d[2][4][4];
#pragma unroll
        for (int a = 0; a < 2; a++)
#pragma unroll
            for (int b = 0; b < 4; b++)
#pragma unroll
                for (int c = 0; c < 4; c++) d[a][b][c] = 0.0f;

        const u64 hglob = gaddr(&g_Hp[layer][e][t - 1][m][0]);
        const u64 wglob = gaddr(&g_Wf[layer][e][s][0]);
        const int crow = tid >> 1, cc2 = (tid & 1) * 4;

#define ISSUE_CHUNK(kc_, st_) do {                                          \
    uint32_t stgb = smb + (st_) * STG_BYTES;                                \
    u64 asrc = hglob + ((u64)(kc_) * 8 + (u64)crow * 128 + cc2) * 16;       \
    uint32_t ada = stgb + (crow * 10 + cc2) * 16;                           \
    asm volatile("cp.async.cg.shared.global [%0], [%1], 16;" :: "r"(ada), "l"(asrc)); \
    asm volatile("cp.async.cg.shared.global [%0], [%1], 16;" :: "r"(ada + 16), "l"(asrc + 16)); \
    asm volatile("cp.async.cg.shared.global [%0], [%1], 16;" :: "r"(ada + 32), "l"(asrc + 32)); \
    asm volatile("cp.async.cg.shared.global [%0], [%1], 16;" :: "r"(ada + 48), "l"(asrc + 48)); \
    u64 wsrc = wglob + (u64)(kc_) * W_ST_BYTES + (u64)tid * 32;             \
    uint32_t wda = stgb + A_ST_BYTES + tid * 32;                            \
    asm volatile("cp.async.cg.shared.global [%0], [%1], 16;" :: "r"(wda), "l"(wsrc)); \
    asm volatile("cp.async.cg.shared.global [%0], [%1], 16;" :: "r"(wda + 16), "l"(wsrc + 16)); \
    asm volatile("cp.async.commit_group;");                                 \
} while (0)

        ISSUE_CHUNK(0, 0);
        ISSUE_CHUNK(1, 1);

        for (int kc = 0; kc < 16; kc++) {
            if (kc < 14)
                asm volatile("cp.async.wait_group 1;" ::: "memory");
            else
                asm volatile("cp.async.wait_group 0;" ::: "memory");
            __syncthreads();
            if (kc + 2 < 16) ISSUE_CHUNK(kc + 2, (kc + 2) % 3);
            const char* stg = sm + (kc % 3) * STG_BYTES;
            const float2* A2  = (const float2*)stg;
            const float2* WBc = (const float2*)(stg + A_ST_BYTES);
#pragma unroll
            for (int k8l = 0; k8l < 4; k8l++) {
                uint2 bf[4];
                const float2* wbp = WBc + ((size_t)k8l * 8 + wn * 4) * 32 + lane;
#pragma unroll
                for (int j = 0; j < 4; j++) bf[j] = *(const uint2*)&wbp[j * 32];
#pragma unroll
                for (int ms = 0; ms < 2; ms++) {
                    int R = wm * 32 + ms * 16;
                    uint2 alo = *(const uint2*)&A2[(R + gid) * A2_PITCH + k8l * 4 + tig];
                    uint2 ahi = *(const uint2*)&A2[(R + 8 + gid) * A2_PITCH + k8l * 4 + tig];
#pragma unroll
                    for (int j = 0; j < 4; j++)
                        mma8(d[ms][j], alo.x, ahi.x, alo.y, ahi.y,
                             bf[j].x, bf[j].y);
                }
            }
        }
#undef ISSUE_CHUNK
        __syncthreads();
        // ---- d -> zs ----
#pragma unroll
        for (int ms = 0; ms < 2; ms++) {
            int r0 = wm * 32 + ms * 16 + gid;
#pragma unroll
            for (int j = 0; j < 4; j++) {
                int c = wn * 32 + j * 8 + tig * 2;
                *(float2*)&zs[r0 * 66 + c] =
                    make_float2(d[ms][j][0], d[ms][j][1]);
                *(float2*)&zs[(r0 + 8) * 66 + c] =
                    make_float2(d[ms][j][2], d[ms][j][3]);
            }
        }
        __syncthreads();
    }

    // ---- epilogue: cell update + h store + c store ----
    {
        float* hw = (float*)&g_Hp[layer][e][t][m][0];
        float* hr = g_H1[e] + ((size_t)t * Bn + m0) * Hn + u0;
        int pofs = s * 16 + ((eu >> 3) << 3) + ((eu & 3) << 1) + ((eu >> 2) & 1);
#pragma unroll
        for (int q = 0; q < 8; q++) {
            int row = erg + 16 * q;
            float zi = xg[0][q], zj = xg[1][q];
            float zf = xg[2][q], zo = xg[3][q];
            if (t > 0) {
                zi += zs[row * 66 + eu];
                zj += zs[row * 66 + 16 + eu];
                zf += zs[row * 66 + 32 + eu];
                zo += zs[row * 66 + 48 + eu];
            }
            float cn = creg[q] * sigf(zf + 1.0f) + sigf(zi) * tanhfast(zj);
            g_c[e][m0 + row][u0 + eu] = cn;
            float hv = tanhfast(cn) * sigf(zo);
            if (layer) hr[(size_t)row * Hn + eu] = hv;
            hw[row * 512 + pofs] = __uint_as_float(cvt_tf32(hv));
        }
    }
}

// ============================================================================
// Gather last valid timestep + final projection [B,1024]@[1024,200]
// ============================================================================
__global__ __launch_bounds__(256) void final_kernel(
    const int* __restrict__ lenL, const int* __restrict__ lenR,
    const float* __restrict__ Wt, float* __restrict__ out)
{
    __shared__ float v[2 * Hn];
    int b = blockIdx.x, tid = threadIdx.x;
    int iL = lenL[b] - 1, iR = lenR[b] - 1;
    const float* hL = &g_H1[0][((size_t)iL * Bn + b) * Hn];
    const float* hR = &g_H1[1][((size_t)iR * Bn + b) * Hn];
    v[tid]       = hL[tid];
    v[256 + tid] = hL[256 + tid];
    v[512 + tid] = hR[tid];
    v[768 + tid] = hR[256 + tid];
    __syncthreads();
    if (tid < OUTD) {
        float acc = 0.0f;
#pragma unroll 8
        for (int k = 0; k < 2 * Hn; k++)
            acc += v[k] * Wt[k * OUTD + tid];
        out[b * OUTD + tid] = acc;
    }
}

// ============================================================================
extern "C" void kernel_launch(void* const* d_in, const int* in_sizes, int n_in,
                              void* d_out, int out_size)
{
    const float* left  = (const float*)d_in[0];
    const float* right = (const float*)d_in[1];
    const int*   lenL  = (const int*)d_in[2];
    const int*   lenR  = (const int*)d_in[3];
    const float* lW0 = (const float*)d_in[4];
    const float* lb0 = (const float*)d_in[5];
    const float* lW1 = (const float*)d_in[6];
    const float* lb1 = (const float*)d_in[7];
    const float* rW0 = (const float*)d_in[8];
    const float* rb0 = (const float*)d_in[9];
    const float* rW1 = (const float*)d_in[10];
    const float* rb1 = (const float*)d_in[11];
    const float* tW  = (const float*)d_in[12];
    float* out = (float*)d_out;

    static int smem_set = 0;
    if (!smem_set) {
        cudaFuncSetAttribute(lstm_step,
                             cudaFuncAttributeMaxDynamicSharedMemorySize, SMEM_STEP);
        smem_set = 1;
    }

    dim3 gx(256, 16, 2);
    dim3 gw(32, 2);

    // W fragment prep (both layers, up front)
    wprep<<<gw, 256>>>(lW0 + (size_t)Dn * G4, rW0 + (size_t)Dn * G4, 0);
    wprep<<<gw, 256>>>(lW1 + (size_t)Hn * G4, rW1 + (size_t)Hn * G4, 1);

    // layer 0
    xproj_mma<<<gx, 256>>>(left, right, lW0, rW0, lb0, rb0, Dn, 0);
    for (int t = 0; t < Tn; t++)
        lstm_step<<<128, 256, SMEM_STEP>>>(t, 0);

    // layer 1 (xproj reads layer-0 pair image directly)
    xproj_mma<<<gx, 256>>>(nullptr, nullptr, lW1, rW1, lb1, rb1, Hn, 1);
    for (int t = 0; t < Tn; t++)
        lstm_step<<<128, 256, SMEM_STEP>>>(t, 1);

    // gather + output projection
    final_kernel<<<256, 256>>>(lenL, lenR, tW, out);
}

// round 10
// speedup vs baseline: 1.2431x; 1.2431x over previous
#include <cuda_runtime.h>
#include <cstdint>

#define Bn 256
#define Tn 128
#define Dn 300
#define Hn 512
#define G4 2048
#define OUTD 200

typedef unsigned long long u64;

// -------- static scratch --------
__device__ float g_X[2][Tn * Bn * G4];        // input projections [t][b][2048]
__device__ float g_H1[2][Tn * Bn * Hn];       // layer1 h row-major (final gather)
// pair-layout h images, tf32-pre-rounded:
// [layer][enc][t][mhalf][row*256 + k8grp*4 + tig] float2 = {h[k], h[k+4]}
__device__ float2 g_Hp[2][2][Tn][2][128 * 256];
__device__ int g_cnt4[4];                      // per-(e,m) group barriers
__device__ int g_gen4[4];

// -------- tf32 / mma helpers --------
__device__ __forceinline__ uint32_t cvt_tf32(float f) {
    uint32_t r;
    asm("cvt.rna.tf32.f32 %0, %1;" : "=r"(r) : "f"(f));
    return r;
}
__device__ __forceinline__ float tf32f(float f) {
    return __uint_as_float(cvt_tf32(f));
}
__device__ __forceinline__ void mma8(float* d, uint32_t a0, uint32_t a1,
                                     uint32_t a2, uint32_t a3,
                                     uint32_t b0, uint32_t b1) {
    asm volatile(
        "mma.sync.aligned.m16n8k8.row.col.f32.tf32.tf32.f32 "
        "{%0,%1,%2,%3}, {%4,%5,%6,%7}, {%8,%9}, {%0,%1,%2,%3};"
        : "+f"(d[0]), "+f"(d[1]), "+f"(d[2]), "+f"(d[3])
        : "r"(a0), "r"(a1), "r"(a2), "r"(a3), "r"(b0), "r"(b1));
}
__device__ __forceinline__ uint32_t smem_u32(const void* p) {
    uint32_t a;
    asm("{ .reg .u64 t; cvta.to.shared.u64 t, %1; cvt.u32.u64 %0, t; }"
        : "=r"(a) : "l"(p));
    return a;
}
__device__ __forceinline__ u64 gaddr(const void* p) {
    u64 g;
    asm("cvta.to.global.u64 %0, %1;" : "=l"(g) : "l"(p));
    return g;
}

// -------- fast activations --------
__device__ __forceinline__ float fast_ex2(float x) {
    float y; asm("ex2.approx.f32 %0, %1;" : "=f"(y) : "f"(x)); return y;
}
__device__ __forceinline__ float fast_rcp(float x) {
    float y; asm("rcp.approx.f32 %0, %1;" : "=f"(y) : "f"(x)); return y;
}
__device__ __forceinline__ float sigf(float x) {
    return fast_rcp(1.0f + fast_ex2(-1.4426950408889634f * x));
}
__device__ __forceinline__ float tanhfast(float x) {
    return 2.0f * fast_rcp(1.0f + fast_ex2(-2.8853900817779268f * x)) - 1.0f;
}

__device__ __forceinline__ float4 gload4(const float* p, int k0, int K) {
    if (k0 + 3 < K) return *(const float4*)p;
    float4 v = make_float4(0.f, 0.f, 0.f, 0.f);
    if (k0 < K)     v.x = p[0];
    if (k0 + 1 < K) v.y = p[1];
    if (k0 + 2 < K) v.z = p[2];
    return v;
}

// ============================================================================
// Input-projection GEMM via tf32 mma.sync (unchanged, proven).
// ============================================================================
#define XP_PITCH 10

__global__ __launch_bounds__(256) void xproj_mma(
    const float* __restrict__ AL, const float* __restrict__ AR,
    const float* __restrict__ WL, const float* __restrict__ WR,
    const float* __restrict__ bL, const float* __restrict__ bR,
    int K, int mode)
{
    __shared__ __align__(16) float2 Apair[128 * XP_PITCH];
    __shared__ __align__(16) float2 Wpair[128 * XP_PITCH];

    const int e = blockIdx.z;
    const float* A    = e ? AR : AL;
    const float* W    = e ? WR : WL;
    const float* bias = e ? bR : bL;
    float* Out = g_X[e];

    const int m0 = blockIdx.x * 128;
    const int n0 = blockIdx.y * 128;
    const int tid = threadIdx.x, lane = tid & 31, wid = tid >> 5;
    const int wm = wid & 1, wn = wid >> 1;
    const int gid = lane >> 2, tig = lane & 3;

    const int tt = m0 >> 8, mh = (m0 >> 7) & 1;

    float d[4][4][4];
#pragma unroll
    for (int a = 0; a < 4; a++)
#pragma unroll
        for (int b = 0; b < 4; b++)
#pragma unroll
            for (int c = 0; c < 4; c++) d[a][b][c] = 0.0f;

    const int arow = tid >> 1, ag = tid & 1;
    const int wg = tid >> 7, wtk = (tid >> 5) & 3, wcc = tid & 31;

    const int nk = (K + 15) >> 4;
    for (int kc16 = 0; kc16 < nk; kc16++) {
        const int kc = kc16 * 16;
        __syncthreads();
        if (mode == 0) {
            int b = (m0 & 255) + arow;
            const float* ap = A + ((size_t)b * Tn + tt) * K + kc + ag * 8;
            int kb = kc + ag * 8;
            float4 lo = (kb     < K) ? gload4(ap, kb, K)
                                     : make_float4(0.f, 0.f, 0.f, 0.f);
            float4 hi = (kb + 4 < K) ? gload4(ap + 4, kb + 4, K)
                                     : make_float4(0.f, 0.f, 0.f, 0.f);
            float2* dst = &Apair[arow * XP_PITCH + ag * 4];
            dst[0] = make_float2(tf32f(lo.x), tf32f(hi.x));
            dst[1] = make_float2(tf32f(lo.y), tf32f(hi.y));
            dst[2] = make_float2(tf32f(lo.z), tf32f(hi.z));
            dst[3] = make_float2(tf32f(lo.w), tf32f(hi.w));
        } else {
            const float4* src = (const float4*)
                &g_Hp[0][e][tt][mh][(size_t)arow * 256 + ((kc >> 3) + ag) * 4];
            float4 v0 = src[0], v1 = src[1];
            float4* dst = (float4*)&Apair[arow * XP_PITCH + ag * 4];
            dst[0] = v0;
            dst[1] = v1;
        }
        {
            int k1 = kc + wg * 8 + wtk, k2 = k1 + 4;
            const float* wp1 = W + (size_t)k1 * G4 + n0 + wcc * 4;
            const float* wp2 = W + (size_t)k2 * G4 + n0 + wcc * 4;
            float4 lo = (k1 < K) ? *(const float4*)wp1
                                 : make_float4(0.f, 0.f, 0.f, 0.f);
            float4 hi = (k2 < K) ? *(const float4*)wp2
                                 : make_float4(0.f, 0.f, 0.f, 0.f);
            int c0 = wcc * 4, pidx = wg * 4 + wtk;
            Wpair[(c0 + 0) * XP_PITCH + pidx] = make_float2(tf32f(lo.x), tf32f(hi.x));
            Wpair[(c0 + 1) * XP_PITCH + pidx] = make_float2(tf32f(lo.y), tf32f(hi.y));
            Wpair[(c0 + 2) * XP_PITCH + pidx] = make_float2(tf32f(lo.z), tf32f(hi.z));
            Wpair[(c0 + 3) * XP_PITCH + pidx] = make_float2(tf32f(lo.w), tf32f(hi.w));
        }
        __syncthreads();
#pragma unroll
        for (int g = 0; g < 2; g++) {
            uint2 bf[4];
#pragma unroll
            for (int j = 0; j < 4; j++) {
                int col = wn * 32 + j * 8 + gid;
                bf[j] = *(const uint2*)&Wpair[col * XP_PITCH + g * 4 + tig];
            }
#pragma unroll
            for (int ms = 0; ms < 4; ms++) {
                int R = wm * 64 + ms * 16;
                uint2 alo = *(const uint2*)&Apair[(R + gid) * XP_PITCH + g * 4 + tig];
                uint2 ahi = *(const uint2*)&Apair[(R + 8 + gid) * XP_PITCH + g * 4 + tig];
#pragma unroll
                for (int j = 0; j < 4; j++)
                    mma8(d[ms][j], alo.x, ahi.x, alo.y, ahi.y, bf[j].x, bf[j].y);
            }
        }
    }

#pragma unroll
    for (int ms = 0; ms < 4; ms++) {
        int r = m0 + wm * 64 + ms * 16 + gid;
#pragma unroll
        for (int j = 0; j < 4; j++) {
            int n = n0 + wn * 32 + j * 8 + tig * 2;
            float2 bv = *(const float2*)&bias[n];
            *(float2*)&Out[(size_t)r * G4 + n] =
                make_float2(d[ms][j][0] + bv.x, d[ms][j][1] + bv.y);
            *(float2*)&Out[(size_t)(r + 8) * G4 + n] =
                make_float2(d[ms][j][2] + bv.x, d[ms][j][3] + bv.y);
        }
    }
}

// ============================================================================
// Persistent tf32 mma.sync LSTM layer — 512 threads, K-split warp groups.
// 128 CTAs = e(2) x m(2) x s(32). CTA: M=128 x N=64 x K=512 per step.
// 16 warps = kgroup(2) x wm(4) x wn(2); warp tile 32x32; each k-group does
// half the k8s of every chunk -> 4 warps/SMSP with UNCHANGED LDS/HMMA totals.
// W fragments resident in smem; h streamed via cp.async 3-stage ring;
// dual zs partial sums reduced in the epilogue. Cell state in registers.
// ============================================================================
#define WB_BYTES  131072
#define ST_BYTES  20480                        // 128 rows x 10 f4
#define ZS_FLTS   (128 * 66)
#define SMEM_DYN  (WB_BYTES + 2 * ZS_FLTS * 4) // 198656 (stages alias zs region)
#define A2_PITCH  20

__global__ __launch_bounds__(512, 1) void lstm_persist_mma(
    const float* __restrict__ WhL, const float* __restrict__ WhR, int layer)
{
    extern __shared__ __align__(16) char sm[];
    float2* WB = (float2*)sm;
    float*  zs0 = (float*)(sm + WB_BYTES);     // aliases stage bufs (post-GEMM)
    float*  zs1 = zs0 + ZS_FLTS;
    const uint32_t smb = smem_u32(sm);
    const uint32_t stg_base = smb + WB_BYTES;

    const int tid = threadIdx.x, lane = tid & 31, wid = tid >> 5;
    const int wk = wid >> 3;                   // k-group 0/1
    const int wm = (wid >> 1) & 3, wn = wid & 1;
    const int gid = lane >> 2, tig = lane & 3;
    const int e = blockIdx.x >> 6;
    const int m = (blockIdx.x >> 5) & 1;
    const int s = blockIdx.x & 31;
    const int grp = blockIdx.x >> 5;
    const int m0 = m * 128, u0 = s * 16;

    const float* Wh = e ? WhR : WhL;
    const float* X  = g_X[e];
    float* Hrow = g_H1[e];

    // ---- precompute W fragments in mma B-register order (tf32) ----
#pragma unroll 4
    for (int i = 0; i < 32; i++) {
        int idx = tid + 512 * i;
        int ln = idx & 31, nt = (idx >> 5) & 7, ks = idx >> 8;
        int n = nt * 8 + (ln >> 2);
        int k = ks * 8 + (ln & 3);
        int col = ((n >> 4) << 9) + u0 + (n & 15);
        uint32_t b0 = cvt_tf32(Wh[(size_t)k * G4 + col]);
        uint32_t b1 = cvt_tf32(Wh[(size_t)(k + 4) * G4 + col]);
        WB[idx] = make_float2(__uint_as_float(b0), __uint_as_float(b1));
    }

    float creg[4];
#pragma unroll
    for (int i = 0; i < 4; i++) creg[i] = 0.0f;
    const int eu = tid & 15, erg = (tid >> 4) & 31;

    // cp.async role: 2 x 16B per chunk (512 thr x 2 f4 = 128 rows x 8 f4)
    const int crow = tid >> 2, cc2 = (tid & 3) * 2;

    // ---- X prefetch for t=0 ----
    float xg[4][4];
    {
        const float* Xt = X + (size_t)m0 * G4 + u0;
#pragma unroll
        for (int q = 0; q < 4; q++) {
            const float* Xb = Xt + (size_t)(erg + 32 * q) * G4;
            xg[0][q] = Xb[eu];
            xg[1][q] = Xb[512 + eu];
            xg[2][q] = Xb[1024 + eu];
            xg[3][q] = Xb[1536 + eu];
        }
    }

    __syncthreads();

    for (int t = 0; t < Tn; t++) {
        if (t > 0) {
            float d[2][4][4];
#pragma unroll
            for (int a = 0; a < 2; a++)
#pragma unroll
                for (int b = 0; b < 4; b++)
#pragma unroll
                    for (int c = 0; c < 4; c++) d[a][b][c] = 0.0f;

            const u64 hglob = gaddr(&g_Hp[layer][e][t - 1][m][0]);

#define ISSUE_CHUNK(kc_, st_) do {                                          \
    uint32_t dstb = stg_base + (st_) * ST_BYTES;                            \
    u64 srcb = hglob + ((u64)(kc_) * 8 + (u64)crow * 128 + cc2) * 16;       \
    uint32_t da = dstb + (crow * 10 + cc2) * 16;                            \
    asm volatile("cp.async.cg.shared.global [%0], [%1], 16;" :: "r"(da), "l"(srcb)); \
    asm volatile("cp.async.cg.shared.global [%0], [%1], 16;" :: "r"(da + 16), "l"(srcb + 16)); \
    asm volatile("cp.async.commit_group;");                                 \
} while (0)

            ISSUE_CHUNK(0, 0);
            ISSUE_CHUNK(1, 1);

            for (int kc = 0; kc < 16; kc++) {
                if (kc < 14)
                    asm volatile("cp.async.wait_group 1;" ::: "memory");
                else
                    asm volatile("cp.async.wait_group 0;" ::: "memory");
                __syncthreads();
                if (kc + 2 < 16) ISSUE_CHUNK(kc + 2, (kc + 2) % 3);
                const float2* A2 =
                    (const float2*)(sm + WB_BYTES + (kc % 3) * ST_BYTES);
#pragma unroll
                for (int j8 = 0; j8 < 2; j8++) {
                    int k8l = wk * 2 + j8;
                    int k8g = kc * 4 + k8l;
                    uint2 bf[4];
                    const float2* wbp = WB + ((size_t)k8g * 8 + wn * 4) * 32 + lane;
#pragma unroll
                    for (int j = 0; j < 4; j++) bf[j] = *(const uint2*)&wbp[j * 32];
#pragma unroll
                    for (int ms = 0; ms < 2; ms++) {
                        int R = wm * 32 + ms * 16;
                        uint2 alo = *(const uint2*)&A2[(R + gid) * A2_PITCH + k8l * 4 + tig];
                        uint2 ahi = *(const uint2*)&A2[(R + 8 + gid) * A2_PITCH + k8l * 4 + tig];
#pragma unroll
                        for (int j = 0; j < 4; j++)
                            mma8(d[ms][j], alo.x, ahi.x, alo.y, ahi.y,
                                 bf[j].x, bf[j].y);
                    }
                }
            }
#undef ISSUE_CHUNK
            __syncthreads();
            // ---- d -> zs (each k-group to its own buffer) ----
            float* zsw = wk ? zs1 : zs0;
#pragma unroll
            for (int ms = 0; ms < 2; ms++) {
                int r0 = wm * 32 + ms * 16 + gid;
#pragma unroll
                for (int j = 0; j < 4; j++) {
                    int c = wn * 32 + j * 8 + tig * 2;
                    *(float2*)&zsw[r0 * 66 + c] =
                        make_float2(d[ms][j][0], d[ms][j][1]);
                    *(float2*)&zsw[(r0 + 8) * 66 + c] =
                        make_float2(d[ms][j][2], d[ms][j][3]);
                }
            }
            __syncthreads();
        }

        // ---- epilogue: cell update + h store (X pre-loaded in xg) ----
        {
            float* hw = (float*)&g_Hp[layer][e][t][m][0];
            float* hr = Hrow + ((size_t)t * Bn + m0) * Hn + u0;
            int pofs = s * 16 + ((eu >> 3) << 3) + ((eu & 3) << 1) + ((eu >> 2) & 1);
#pragma unroll
            for (int q = 0; q < 4; q++) {
                int row = erg + 32 * q;
                float zi = xg[0][q], zj = xg[1][q];
                float zf = xg[2][q], zo = xg[3][q];
                if (t > 0) {
                    zi += zs0[row * 66 + eu]      + zs1[row * 66 + eu];
                    zj += zs0[row * 66 + 16 + eu] + zs1[row * 66 + 16 + eu];
                    zf += zs0[row * 66 + 32 + eu] + zs1[row * 66 + 32 + eu];
                    zo += zs0[row * 66 + 48 + eu] + zs1[row * 66 + 48 + eu];
                }
                float cn = creg[q] * sigf(zf + 1.0f) + sigf(zi) * tanhfast(zj);
                creg[q] = cn;
                float hv = tanhfast(cn) * sigf(zo);
                if (layer) hr[(size_t)row * Hn + eu] = hv;
                hw[row * 512 + pofs] = __uint_as_float(cvt_tf32(hv));
            }
        }

        if (t != Tn - 1) {
            // ---- prefetch X[t+1] (overlaps barrier + next GEMM) ----
            {
                const float* Xt = X + ((size_t)(t + 1) * Bn + m0) * G4 + u0;
#pragma unroll
                for (int q = 0; q < 4; q++) {
                    const float* Xb = Xt + (size_t)(erg + 32 * q) * G4;
                    xg[0][q] = Xb[eu];
                    xg[1][q] = Xb[512 + eu];
                    xg[2][q] = Xb[1024 + eu];
                    xg[3][q] = Xb[1536 + eu];
                }
            }
            // ---- per-(e,m) group barrier (32 CTAs) ----
            __threadfence();
            __syncthreads();
            if (tid == 0) {
                int g = *((volatile int*)&g_gen4[grp]);
                if (atomicAdd(&g_cnt4[grp], 1) == 31) {
                    g_cnt4[grp] = 0;
                    __threadfence();
                    atomicAdd(&g_gen4[grp], 1);
                } else {
                    while (*((volatile int*)&g_gen4[grp]) == g) { }
                }
            }
            __syncthreads();
        }
    }
}

// ============================================================================
// Gather last valid timestep + final projection [B,1024]@[1024,200]
// ============================================================================
__global__ __launch_bounds__(256) void final_kernel(
    const int* __restrict__ lenL, const int* __restrict__ lenR,
    const float* __restrict__ Wt, float* __restrict__ out)
{
    __shared__ float v[2 * Hn];
    int b = blockIdx.x, tid = threadIdx.x;
    int iL = lenL[b] - 1, iR = lenR[b] - 1;
    const float* hL = &g_H1[0][((size_t)iL * Bn + b) * Hn];
    const float* hR = &g_H1[1][((size_t)iR * Bn + b) * Hn];
    v[tid]       = hL[tid];
    v[256 + tid] = hL[256 + tid];
    v[512 + tid] = hR[tid];
    v[768 + tid] = hR[256 + tid];
    __syncthreads();
    if (tid < OUTD) {
        float acc = 0.0f;
#pragma unroll 8
        for (int k = 0; k < 2 * Hn; k++)
            acc += v[k] * Wt[k * OUTD + tid];
        out[b * OUTD + tid] = acc;
    }
}

// ============================================================================
extern "C" void kernel_launch(void* const* d_in, const int* in_sizes, int n_in,
                              void* d_out, int out_size)
{
    const float* left  = (const float*)d_in[0];
    const float* right = (const float*)d_in[1];
    const int*   lenL  = (const int*)d_in[2];
    const int*   lenR  = (const int*)d_in[3];
    const float* lW0 = (const float*)d_in[4];
    const float* lb0 = (const float*)d_in[5];
    const float* lW1 = (const float*)d_in[6];
    const float* lb1 = (const float*)d_in[7];
    const float* rW0 = (const float*)d_in[8];
    const float* rb0 = (const float*)d_in[9];
    const float* rW1 = (const float*)d_in[10];
    const float* rb1 = (const float*)d_in[11];
    const float* tW  = (const float*)d_in[12];
    float* out = (float*)d_out;

    static int smem_set = 0;
    if (!smem_set) {
        cudaFuncSetAttribute(lstm_persist_mma,
                             cudaFuncAttributeMaxDynamicSharedMemorySize, SMEM_DYN);
        smem_set = 1;
    }

    dim3 gx(256, 16, 2);

    // layer 0
    xproj_mma<<<gx, 256>>>(left, right, lW0, rW0, lb0, rb0, Dn, 0);
    lstm_persist_mma<<<128, 512, SMEM_DYN>>>(lW0 + (size_t)Dn * G4,
                                             rW0 + (size_t)Dn * G4, 0);
    // layer 1 (reads layer-0 pair image directly)
    xproj_mma<<<gx, 256>>>(nullptr, nullptr, lW1, rW1, lb1, rb1, Hn, 1);
    lstm_persist_mma<<<128, 512, SMEM_DYN>>>(lW1 + (size_t)Hn * G4,
                                             rW1 + (size_t)Hn * G4, 1);
    // gather + output projection
    final_kernel<<<256, 256>>>(lenL, lenR, tW, out);
}